// round 17
// baseline (speedup 1.0000x reference)
#include <cuda_runtime.h>
#include <cuda_fp16.h>
#include <math_constants.h>

#define Nn 50000
#define Dd 128
#define Ee 800000
#define CAP 64
#define LRELU_ALPHA 0.2f

#define GEMM_BLOCKS 148        // one 256-thr gemm block per SM
#define SCAT_BLOCKS 148        // one 256-thr scatter block per SM (b+148 -> SM b)
#define SC_THREADS (SCAT_BLOCKS * 256)
#define NTILES 3125            // 50000 / 16

// Scratch (device globals -- no allocation allowed)
__device__ __align__(16) __half g_Whh[(size_t)Nn * Dd];  // 12.8 MB, L2-resident
__device__ float g_sv[Nn];
__device__ float g_dv[Nn];
__device__ __align__(16) int g_cnt[Nn];
__device__ int   g_srcs[(size_t)Nn * CAP];               // direct-mapped CSR
// scatter-block barrier state (returns to all-zero at end of every run)
__device__ int g_bar, g_go, g_done;

__device__ __forceinline__ unsigned tf32(float f) {
    unsigned u; asm("cvt.rna.tf32.f32 %0, %1;" : "=r"(u) : "f"(f)); return u;
}
__device__ __forceinline__ void mma_tf32(float c[4], const unsigned a[4], const unsigned b[2]) {
    asm volatile(
        "mma.sync.aligned.m16n8k8.row.col.f32.tf32.tf32.f32 "
        "{%0,%1,%2,%3}, {%4,%5,%6,%7}, {%8,%9}, {%0,%1,%2,%3};"
        : "+f"(c[0]), "+f"(c[1]), "+f"(c[2]), "+f"(c[3])
        : "r"(a[0]), "r"(a[1]), "r"(a[2]), "r"(a[3]), "r"(b[0]), "r"(b[1]));
}

// ---------------------------------------------------------------------------
// K1: block-role build, 256-thread blocks.
//   bid < 148:  persistent tf32-mma gemm, 8 warps x 16 output columns
//               (R16 structure -- measured win; unchanged).
//   bid >= 148: zero g_cnt chunk -> resident-wave go-flag barrier -> scatter.
//               All 296 blocks are wave-1 resident, so the barrier among the
//               148 scatter blocks cannot deadlock. Replaces the k_reset
//               launch (3.9us) with ~2us hidden mostly under gemm slack.
// ---------------------------------------------------------------------------
__global__ __launch_bounds__(256, 2)
void k_build(const float* __restrict__ h, const float* __restrict__ W,
             const float* __restrict__ a,
             const int4* __restrict__ src4, const int4* __restrict__ dst4) {
    if (blockIdx.x >= GEMM_BLOCKS) {
        const int sb = blockIdx.x - GEMM_BLOCKS;

        // ---- zero this block's chunk of g_cnt (int4-wide) ----
        for (int i = sb * 256 + threadIdx.x; i < Nn / 4; i += SC_THREADS)
            ((int4*)g_cnt)[i] = make_int4(0, 0, 0, 0);
        __syncthreads();

        // ---- barrier across the 148 scatter blocks (go-flag release) ----
        if (threadIdx.x == 0) {
            __threadfence();                          // publish zero stores
            int t = atomicAdd(&g_bar, 1);
            if (t == SCAT_BLOCKS - 1) atomicExch(&g_go, 1);
            while (*(volatile int*)&g_go == 0) __nanosleep(64);
            __threadfence();                          // acquire
        }
        __syncthreads();

        // ---- scatter: 4 edges per int4, grid-stride ----
        for (int i = sb * 256 + threadIdx.x; i < Ee / 4; i += SC_THREADS) {
            int4 s = src4[i], d = dst4[i];
            int sl;
            sl = atomicAdd(&g_cnt[d.x], 1); if (sl < CAP) g_srcs[d.x * CAP + sl] = s.x;
            sl = atomicAdd(&g_cnt[d.y], 1); if (sl < CAP) g_srcs[d.y * CAP + sl] = s.y;
            sl = atomicAdd(&g_cnt[d.z], 1); if (sl < CAP) g_srcs[d.z * CAP + sl] = s.z;
            sl = atomicAdd(&g_cnt[d.w], 1); if (sl < CAP) g_srcs[d.w * CAP + sl] = s.w;
        }
        __syncthreads();

        // ---- restore barrier state to all-zero for the next replay ----
        if (threadIdx.x == 0) {
            int dn = atomicAdd(&g_done, 1);
            if (dn == SCAT_BLOCKS - 1) {   // all blocks passed spin & scatter
                g_bar = 0; g_done = 0;
                __threadfence();
                *(volatile int*)&g_go = 0;
            }
        }
        return;
    }

    // ----- gemm role: 8 warps, 16 columns per warp (EXACT R16) -----
    __shared__ __align__(16) unsigned sh[16][132];
    __shared__ float ssv[8][16], sdv[8][16];
    const int lane  = threadIdx.x & 31;
    const int wn    = threadIdx.x >> 5;          // 0..7
    const int ncol0 = wn * 16;
    const int r     = lane >> 2;
    const int cc    = 2 * (lane & 3);

    unsigned b[16][2][2];
#pragma unroll
    for (int ks = 0; ks < 16; ks++)
#pragma unroll
        for (int j = 0; j < 2; j++) {
            int n  = ncol0 + j * 8 + (lane >> 2);
            int k0 = ks * 8 + (lane & 3);
            b[ks][j][0] = tf32(W[k0 * Dd + n]);
            b[ks][j][1] = tf32(W[(k0 + 4) * Dd + n]);
        }
    float2 as[2], ad[2];
#pragma unroll
    for (int j = 0; j < 2; j++) {
        int col = ncol0 + j * 8 + cc;
        as[j] = make_float2(a[col], a[col + 1]);
        ad[j] = make_float2(a[Dd + col], a[Dd + col + 1]);
    }

    float4 pre[2];
    {
        const float4* hsrc = (const float4*)(h + (size_t)blockIdx.x * 16 * Dd);
#pragma unroll
        for (int t = 0; t < 2; t++) pre[t] = hsrc[threadIdx.x + t * 256];
    }

    for (int tile = blockIdx.x; tile < NTILES; tile += GEMM_BLOCKS) {
        const int base = tile * 16;

#pragma unroll
        for (int t = 0; t < 2; t++) {
            int idx = threadIdx.x + t * 256;
            int rr = idx >> 5, c2 = idx & 31;
            *(uint4*)&sh[rr][c2 * 4] = make_uint4(
                tf32(pre[t].x), tf32(pre[t].y), tf32(pre[t].z), tf32(pre[t].w));
        }
        __syncthreads();

        const int ntile = tile + GEMM_BLOCKS;
        if (ntile < NTILES) {
            const float4* hsrc = (const float4*)(h + (size_t)ntile * 16 * Dd);
#pragma unroll
            for (int t = 0; t < 2; t++) pre[t] = hsrc[threadIdx.x + t * 256];
        }

        float c[2][4];
#pragma unroll
        for (int j = 0; j < 2; j++)
#pragma unroll
            for (int q = 0; q < 4; q++) c[j][q] = 0.0f;

#pragma unroll
        for (int ks = 0; ks < 16; ks++) {
            const int kc = ks * 8 + (lane & 3);
            unsigned av[4];
            av[0] = sh[r][kc];
            av[1] = sh[r + 8][kc];
            av[2] = sh[r][kc + 4];
            av[3] = sh[r + 8][kc + 4];
#pragma unroll
            for (int j = 0; j < 2; j++) mma_tf32(c[j], av, b[ks][j]);
        }

        float vs0 = 0.f, vs1 = 0.f, vd0 = 0.f, vd1 = 0.f;
#pragma unroll
        for (int j = 0; j < 2; j++) {
            int col = ncol0 + j * 8 + cc;
            *(__half2*)&g_Whh[(size_t)(base + r) * Dd + col] =
                __floats2half2_rn(c[j][0], c[j][1]);
            *(__half2*)&g_Whh[(size_t)(base + r + 8) * Dd + col] =
                __floats2half2_rn(c[j][2], c[j][3]);
            vs0 = fmaf(c[j][0], as[j].x, fmaf(c[j][1], as[j].y, vs0));
            vs1 = fmaf(c[j][2], as[j].x, fmaf(c[j][3], as[j].y, vs1));
            vd0 = fmaf(c[j][0], ad[j].x, fmaf(c[j][1], ad[j].y, vd0));
            vd1 = fmaf(c[j][2], ad[j].x, fmaf(c[j][3], ad[j].y, vd1));
        }
#pragma unroll
        for (int off = 1; off <= 2; off <<= 1) {
            vs0 += __shfl_xor_sync(0xffffffffu, vs0, off);
            vs1 += __shfl_xor_sync(0xffffffffu, vs1, off);
            vd0 += __shfl_xor_sync(0xffffffffu, vd0, off);
            vd1 += __shfl_xor_sync(0xffffffffu, vd1, off);
        }
        if ((lane & 3) == 0) {
            ssv[wn][r] = vs0; ssv[wn][r + 8] = vs1;
            sdv[wn][r] = vd0; sdv[wn][r + 8] = vd1;
        }
        __syncthreads();
        if (threadIdx.x < 16) {
            int t = threadIdx.x;
            g_sv[base + t] = ((ssv[0][t] + ssv[1][t]) + (ssv[2][t] + ssv[3][t]))
                           + ((ssv[4][t] + ssv[5][t]) + (ssv[6][t] + ssv[7][t]));
        } else if (threadIdx.x >= 32 && threadIdx.x < 48) {
            int t = threadIdx.x - 32;
            g_dv[base + t] = ((sdv[0][t] + sdv[1][t]) + (sdv[2][t] + sdv[3][t]))
                           + ((sdv[4][t] + sdv[5][t]) + (sdv[6][t] + sdv[7][t]));
        }
    }
}

// ---------------------------------------------------------------------------
// K2: fused per-node softmax + aggregation + residual. One warp per node.
// EXACT R5 kernel (measured 27.4us). NO g_cnt write (empirically toxic).
// ---------------------------------------------------------------------------
__global__ __launch_bounds__(256)
void k_node(const float* __restrict__ h, float* __restrict__ out) {
    __shared__ float2 stage[8][CAP];
    const int warp = threadIdx.x >> 5;
    const int lane = threadIdx.x & 31;
    const int v    = blockIdx.x * 8 + warp;
    if (v >= Nn) return;

    float4 acc = ((const float4*)h)[v * 32 + lane];  // residual
    int cnt = g_cnt[v];
    cnt = cnt < CAP ? cnt : CAP;

    if (cnt > 0) {
        const float dvv = g_dv[v];
        const int* sp = g_srcs + v * CAP;

        int s0 = 0, s1 = 0;
        float e0 = -CUDART_INF_F, e1 = -CUDART_INF_F;
        if (lane < cnt) {
            s0 = sp[lane];
            float e = g_sv[s0] + dvv;
            e0 = (e > 0.0f) ? e : LRELU_ALPHA * e;
        }
        if (lane + 32 < cnt) {
            s1 = sp[lane + 32];
            float e = g_sv[s1] + dvv;
            e1 = (e > 0.0f) ? e : LRELU_ALPHA * e;
        }

        float m = fmaxf(e0, e1);
#pragma unroll
        for (int off = 16; off; off >>= 1)
            m = fmaxf(m, __shfl_xor_sync(0xffffffffu, m, off));

        float ex0 = (lane < cnt)      ? __expf(e0 - m) : 0.0f;
        float ex1 = (lane + 32 < cnt) ? __expf(e1 - m) : 0.0f;
        float sum = ex0 + ex1;
#pragma unroll
        for (int off = 16; off; off >>= 1)
            sum += __shfl_xor_sync(0xffffffffu, sum, off);
        const float inv = 1.0f / sum;

        stage[warp][lane]      = make_float2(ex0 * inv, __int_as_float(s0));
        stage[warp][lane + 32] = make_float2(ex1 * inv, __int_as_float(s1));
        __syncwarp();

        const uint2* Whh = (const uint2*)g_Whh;   // 8B = 4 halfs per lane
        int i = 0;
        for (; i + 4 <= cnt; i += 4) {
            float2 p0 = stage[warp][i + 0];
            float2 p1 = stage[warp][i + 1];
            float2 p2 = stage[warp][i + 2];
            float2 p3 = stage[warp][i + 3];
            uint2 u0 = Whh[__float_as_int(p0.y) * 32 + lane];
            uint2 u1 = Whh[__float_as_int(p1.y) * 32 + lane];
            uint2 u2 = Whh[__float_as_int(p2.y) * 32 + lane];
            uint2 u3 = Whh[__float_as_int(p3.y) * 32 + lane];
#define ACC(u, al)                                                         \
            {                                                              \
                float2 lo = __half22float2(*(__half2*)&(u).x);             \
                float2 hi = __half22float2(*(__half2*)&(u).y);             \
                acc.x = fmaf((al), lo.x, acc.x);                           \
                acc.y = fmaf((al), lo.y, acc.y);                           \
                acc.z = fmaf((al), hi.x, acc.z);                           \
                acc.w = fmaf((al), hi.y, acc.w);                           \
            }
            ACC(u0, p0.x) ACC(u1, p1.x) ACC(u2, p2.x) ACC(u3, p3.x)
        }
        for (; i < cnt; i++) {
            float2 p = stage[warp][i];
            uint2 u = Whh[__float_as_int(p.y) * 32 + lane];
            ACC(u, p.x)
        }
#undef ACC
    }

    ((float4*)out)[v * 32 + lane] = acc;
}

// ---------------------------------------------------------------------------
extern "C" void kernel_launch(void* const* d_in, const int* in_sizes, int n_in,
                              void* d_out, int out_size) {
    const float* h   = (const float*)d_in[0];
    const float* W   = (const float*)d_in[1];
    const float* a   = (const float*)d_in[2];
    const int*   src = (const int*)d_in[3];
    const int*   dst = (const int*)d_in[4];
    float*       out = (float*)d_out;

    k_build<<<GEMM_BLOCKS + SCAT_BLOCKS, 256>>>(h, W, a,
                                                (const int4*)src, (const int4*)dst);
    k_node <<<(Nn + 7) / 8, 256>>>(h, out);
}